// round 1
// baseline (speedup 1.0000x reference)
#include <cuda_runtime.h>
#include <cstdint>

// Problem constants
#define NN 50000
#define EE 800000
#define HD 512
#define IND 256
#define OUTD 64

// ---------------- Scratch (static device globals; no allocation APIs) -------
__device__ __align__(16) int   g_src[EE];
__device__ __align__(16) int   g_dst[EE];
__device__ __align__(16) int   g_counts[NN];
__device__ __align__(16) int   g_off[NN + 1];
__device__ __align__(16) int   g_cursor[NN];
__device__ __align__(16) float g_dinv[NN];
__device__ __align__(16) int   g_csr_src[EE];
__device__ __align__(16) float g_xw[(size_t)NN * HD];  // 102.4 MB
__device__ __align__(16) float g_h[(size_t)NN * HD];   // 102.4 MB
__device__ int g_flag;            // 1 = edge_index stored as int64, 0 = int32
__device__ int g_blocksums[64];

// ---------------- Edge dtype detection --------------------------------------
// If int64 little-endian with values < 2^31, every odd int32 word is 0.
__global__ void detect_kernel(const int* __restrict__ raw) {
    __shared__ int any;
    if (threadIdx.x == 0) any = 0;
    __syncthreads();
    int v = raw[2 * threadIdx.x + 1];
    if (v != 0) atomicOr(&any, 1);
    __syncthreads();
    if (threadIdx.x == 0) g_flag = any ? 0 : 1;
}

__global__ void zero_counts_kernel() {
    int i = blockIdx.x * blockDim.x + threadIdx.x;
    if (i < NN) { g_counts[i] = 0; g_cursor[i] = 0; }
}

__global__ void convert_edges_kernel(const int* __restrict__ raw) {
    int e = blockIdx.x * blockDim.x + threadIdx.x;
    if (e >= EE) return;
    int s, d;
    if (g_flag) { s = raw[2 * e]; d = raw[2 * (EE + e)]; }
    else        { s = raw[e];     d = raw[EE + e]; }
    g_src[e] = s;
    g_dst[e] = d;
    atomicAdd(&g_counts[d], 1);
}

__global__ void dinv_kernel() {
    int i = blockIdx.x * blockDim.x + threadIdx.x;
    if (i < NN) g_dinv[i] = rsqrtf((float)(g_counts[i] + 1));  // +1 self-loop
}

// ---------------- Exclusive scan of counts -> offsets ------------------------
#define SCAN_BLK 1024
#define SCAN_NBLK ((NN + SCAN_BLK - 1) / SCAN_BLK)   // 49

__global__ void scan1_kernel() {
    __shared__ int s[SCAN_BLK];
    int i = blockIdx.x * SCAN_BLK + threadIdx.x;
    int v = (i < NN) ? g_counts[i] : 0;
    s[threadIdx.x] = v;
    __syncthreads();
    for (int d = 1; d < SCAN_BLK; d <<= 1) {
        int t = (threadIdx.x >= d) ? s[threadIdx.x - d] : 0;
        __syncthreads();
        s[threadIdx.x] += t;
        __syncthreads();
    }
    if (i < NN) g_off[i] = s[threadIdx.x] - v;   // exclusive within block
    if (threadIdx.x == SCAN_BLK - 1) g_blocksums[blockIdx.x] = s[SCAN_BLK - 1];
}

__global__ void scan2_kernel() {
    if (threadIdx.x == 0) {
        int acc = 0;
        for (int b = 0; b < SCAN_NBLK; b++) {
            int t = g_blocksums[b];
            g_blocksums[b] = acc;
            acc += t;
        }
    }
}

__global__ void scan3_kernel() {
    int i = blockIdx.x * SCAN_BLK + threadIdx.x;
    if (i < NN) g_off[i] += g_blocksums[blockIdx.x];
    if (i == 0) g_off[NN] = EE;
}

__global__ void scatter_kernel() {
    int e = blockIdx.x * blockDim.x + threadIdx.x;
    if (e >= EE) return;
    int d = g_dst[e];
    int pos = g_off[d] + atomicAdd(&g_cursor[d], 1);
    g_csr_src[pos] = g_src[e];
}

// ---------------- Tiled SGEMM ------------------------------------------------
// C[M,N] = A[M,K] @ B[K,N] (+ bias). A,B,C row-major. K % BK == 0, N % BN == 0.
template <int BM, int BN, int BK, int TM, int TN, bool BIAS>
__global__ void sgemm_kernel(const float* __restrict__ A,
                             const float* __restrict__ B,
                             const float* __restrict__ bias,
                             float* __restrict__ C,
                             int M, int N, int K) {
    constexpr int THREADS = (BM / TM) * (BN / TN);
    __shared__ float As[BK][BM];
    __shared__ float Bs[BK][BN];

    int tid = threadIdx.x;
    int tcol = tid % (BN / TN);
    int trow = tid / (BN / TN);
    int rowBase = blockIdx.y * BM;
    int colBase = blockIdx.x * BN;

    float acc[TM][TN];
#pragma unroll
    for (int i = 0; i < TM; i++)
#pragma unroll
        for (int j = 0; j < TN; j++) acc[i][j] = 0.f;

    for (int k0 = 0; k0 < K; k0 += BK) {
        // Load A tile (BM x BK), transpose into As[k][m]
#pragma unroll
        for (int idx = tid * 4; idx < BM * BK; idx += THREADS * 4) {
            int r = idx / BK;
            int c = idx % BK;
            int grow = rowBase + r;
            float4 v = make_float4(0.f, 0.f, 0.f, 0.f);
            if (grow < M)
                v = *(const float4*)(A + (size_t)grow * K + k0 + c);
            As[c + 0][r] = v.x;
            As[c + 1][r] = v.y;
            As[c + 2][r] = v.z;
            As[c + 3][r] = v.w;
        }
        // Load B tile (BK x BN)
#pragma unroll
        for (int idx = tid * 4; idx < BK * BN; idx += THREADS * 4) {
            int r = idx / BN;
            int c = idx % BN;
            *(float4*)&Bs[r][c] = *(const float4*)(B + (size_t)(k0 + r) * N + colBase + c);
        }
        __syncthreads();

#pragma unroll
        for (int kk = 0; kk < BK; kk++) {
            float ar[TM], br[TN];
#pragma unroll
            for (int i = 0; i < TM; i++) ar[i] = As[kk][trow * TM + i];
#pragma unroll
            for (int j = 0; j < TN; j++) br[j] = Bs[kk][tcol * TN + j];
#pragma unroll
            for (int i = 0; i < TM; i++)
#pragma unroll
                for (int j = 0; j < TN; j++) acc[i][j] = fmaf(ar[i], br[j], acc[i][j]);
        }
        __syncthreads();
    }

#pragma unroll
    for (int i = 0; i < TM; i++) {
        int grow = rowBase + trow * TM + i;
        if (grow >= M) continue;
#pragma unroll
        for (int j4 = 0; j4 < TN; j4 += 4) {
            int gcol = colBase + tcol * TN + j4;
            float4 v;
            v.x = acc[i][j4 + 0];
            v.y = acc[i][j4 + 1];
            v.z = acc[i][j4 + 2];
            v.w = acc[i][j4 + 3];
            if constexpr (BIAS) {
                float4 b = *(const float4*)(bias + gcol);
                v.x += b.x; v.y += b.y; v.z += b.z; v.w += b.w;
            }
            *(float4*)(C + (size_t)grow * N + gcol) = v;
        }
    }
}

// ---------------- Gather aggregation (warp per node), fused bias+self+ReLU ---
__global__ void aggregate_kernel(const float* __restrict__ xw,
                                 const float* __restrict__ bias,
                                 float* __restrict__ out) {
    int warp = (blockIdx.x * blockDim.x + threadIdx.x) >> 5;
    int lane = threadIdx.x & 31;
    if (warp >= NN) return;
    int i = warp;

    float di = g_dinv[i];
    float self = di * di;

    const float4* xrow = (const float4*)(xw + (size_t)i * HD);
    const float4* brow = (const float4*)bias;
    float4 acc[4];
#pragma unroll
    for (int c = 0; c < 4; c++) {
        float4 v = xrow[lane + 32 * c];
        float4 b = brow[lane + 32 * c];
        acc[c].x = fmaf(v.x, self, b.x);
        acc[c].y = fmaf(v.y, self, b.y);
        acc[c].z = fmaf(v.z, self, b.z);
        acc[c].w = fmaf(v.w, self, b.w);
    }

    int beg = g_off[i];
    int cnt = g_counts[i];
    for (int t = 0; t < cnt; t++) {
        int s = g_csr_src[beg + t];
        float w = g_dinv[s] * di;
        const float4* srow = (const float4*)(xw + (size_t)s * HD);
#pragma unroll
        for (int c = 0; c < 4; c++) {
            float4 v = srow[lane + 32 * c];
            acc[c].x = fmaf(v.x, w, acc[c].x);
            acc[c].y = fmaf(v.y, w, acc[c].y);
            acc[c].z = fmaf(v.z, w, acc[c].z);
            acc[c].w = fmaf(v.w, w, acc[c].w);
        }
    }

    float4* orow = (float4*)(out + (size_t)i * HD);
#pragma unroll
    for (int c = 0; c < 4; c++) {
        float4 v;
        v.x = fmaxf(acc[c].x, 0.f);
        v.y = fmaxf(acc[c].y, 0.f);
        v.z = fmaxf(acc[c].z, 0.f);
        v.w = fmaxf(acc[c].w, 0.f);
        orow[lane + 32 * c] = v;
    }
}

// ---------------- Launch -----------------------------------------------------
extern "C" void kernel_launch(void* const* d_in, const int* in_sizes, int n_in,
                              void* d_out, int out_size) {
    const float* x  = (const float*)d_in[0];
    const int*   ei = (const int*)d_in[1];   // int32 OR int64, detected on device
    const float* W1 = (const float*)d_in[2];
    const float* b1 = (const float*)d_in[3];
    const float* W2 = (const float*)d_in[4];
    const float* b2 = (const float*)d_in[5];
    const float* Wl = (const float*)d_in[6];
    const float* bl = (const float*)d_in[7];
    float* out = (float*)d_out;

    float* xw;  cudaGetSymbolAddress((void**)&xw, g_xw);
    float* h;   cudaGetSymbolAddress((void**)&h,  g_h);

    // Graph prep (cheap, ~100us)
    detect_kernel<<<1, 256>>>(ei);
    zero_counts_kernel<<<(NN + 255) / 256, 256>>>();
    convert_edges_kernel<<<(EE + 255) / 256, 256>>>(ei);
    dinv_kernel<<<(NN + 255) / 256, 256>>>();
    scan1_kernel<<<SCAN_NBLK, SCAN_BLK>>>();
    scan2_kernel<<<1, 32>>>();
    scan3_kernel<<<SCAN_NBLK, SCAN_BLK>>>();
    scatter_kernel<<<(EE + 255) / 256, 256>>>();

    // Layer 1: xw = x @ W1 ; h = relu(aggregate(xw) + b1)
    {
        dim3 grid(HD / 128, (NN + 127) / 128);
        sgemm_kernel<128, 128, 8, 8, 8, false><<<grid, 256>>>(x, W1, nullptr, xw, NN, HD, IND);
        aggregate_kernel<<<(NN * 32 + 255) / 256, 256>>>(xw, b1, h);
    }
    // Layer 2: xw = h @ W2 ; h = relu(aggregate(xw) + b2)
    {
        dim3 grid(HD / 128, (NN + 127) / 128);
        sgemm_kernel<128, 128, 8, 8, 8, false><<<grid, 256>>>(h, W2, nullptr, xw, NN, HD, HD);
        aggregate_kernel<<<(NN * 32 + 255) / 256, 256>>>(xw, b2, h);
    }
    // Output: out = h @ Wl + bl
    {
        dim3 grid(OUTD / 64, (NN + 127) / 128);
        sgemm_kernel<128, 64, 8, 8, 8, true><<<grid, 128>>>(h, Wl, bl, out, NN, OUTD, HD);
    }
}

// round 2
// speedup vs baseline: 1.6429x; 1.6429x over previous
#include <cuda_runtime.h>
#include <cstdint>

// Problem constants
#define NN 50000
#define EE 800000
#define HD 512
#define IND 256
#define OUTD 64

// ---------------- Scratch (static device globals; no allocation APIs) -------
__device__ __align__(16) int   g_src[EE];
__device__ __align__(16) int   g_dst[EE];
__device__ __align__(16) int   g_counts[NN];
__device__ __align__(16) int   g_off[NN + 1];
__device__ __align__(16) int   g_cursor[NN];
__device__ __align__(16) float g_dinv[NN];
__device__ __align__(16) int   g_csr_src[EE];
__device__ __align__(16) float g_xw[(size_t)NN * HD];  // 102.4 MB
__device__ __align__(16) float g_h[(size_t)NN * HD];   // 102.4 MB
__device__ int g_flag;            // 1 = edge_index stored as int64, 0 = int32
__device__ int g_blocksums[64];

// ---------------- Edge dtype detection --------------------------------------
__global__ void detect_kernel(const int* __restrict__ raw) {
    __shared__ int any;
    if (threadIdx.x == 0) any = 0;
    __syncthreads();
    int v = raw[2 * threadIdx.x + 1];
    if (v != 0) atomicOr(&any, 1);
    __syncthreads();
    if (threadIdx.x == 0) g_flag = any ? 0 : 1;
}

__global__ void zero_counts_kernel() {
    int i = blockIdx.x * blockDim.x + threadIdx.x;
    if (i < NN) { g_counts[i] = 0; g_cursor[i] = 0; }
}

__global__ void convert_edges_kernel(const int* __restrict__ raw) {
    int e = blockIdx.x * blockDim.x + threadIdx.x;
    if (e >= EE) return;
    int s, d;
    if (g_flag) { s = raw[2 * e]; d = raw[2 * (EE + e)]; }
    else        { s = raw[e];     d = raw[EE + e]; }
    g_src[e] = s;
    g_dst[e] = d;
    atomicAdd(&g_counts[d], 1);
}

__global__ void dinv_kernel() {
    int i = blockIdx.x * blockDim.x + threadIdx.x;
    if (i < NN) g_dinv[i] = rsqrtf((float)(g_counts[i] + 1));  // +1 self-loop
}

// ---------------- Exclusive scan of counts -> offsets ------------------------
#define SCAN_BLK 1024
#define SCAN_NBLK ((NN + SCAN_BLK - 1) / SCAN_BLK)   // 49

__global__ void scan1_kernel() {
    __shared__ int s[SCAN_BLK];
    int i = blockIdx.x * SCAN_BLK + threadIdx.x;
    int v = (i < NN) ? g_counts[i] : 0;
    s[threadIdx.x] = v;
    __syncthreads();
    for (int d = 1; d < SCAN_BLK; d <<= 1) {
        int t = (threadIdx.x >= d) ? s[threadIdx.x - d] : 0;
        __syncthreads();
        s[threadIdx.x] += t;
        __syncthreads();
    }
    if (i < NN) g_off[i] = s[threadIdx.x] - v;   // exclusive within block
    if (threadIdx.x == SCAN_BLK - 1) g_blocksums[blockIdx.x] = s[SCAN_BLK - 1];
}

__global__ void scan2_kernel() {
    if (threadIdx.x == 0) {
        int acc = 0;
        for (int b = 0; b < SCAN_NBLK; b++) {
            int t = g_blocksums[b];
            g_blocksums[b] = acc;
            acc += t;
        }
    }
}

__global__ void scan3_kernel() {
    int i = blockIdx.x * SCAN_BLK + threadIdx.x;
    if (i < NN) g_off[i] += g_blocksums[blockIdx.x];
    if (i == 0) g_off[NN] = EE;
}

__global__ void scatter_kernel() {
    int e = blockIdx.x * blockDim.x + threadIdx.x;
    if (e >= EE) return;
    int d = g_dst[e];
    int pos = g_off[d] + atomicAdd(&g_cursor[d], 1);
    g_csr_src[pos] = g_src[e];
}

// ---------------- TF32 tensor-core GEMM --------------------------------------
// C[M,N] = A[M,K] @ B[K,N] (+ bias). Row-major. K % 32 == 0, N % BN == 0.
__device__ __forceinline__ unsigned f2tf32(float x) {
    unsigned r;
    asm("cvt.rna.tf32.f32 %0, %1;" : "=r"(r) : "f"(x));
    return r;
}

template <int BM, int BN, int WARPS_M, int WARPS_N, bool BIAS>
__global__ __launch_bounds__(WARPS_M * WARPS_N * 32)
void tf32_gemm_kernel(const float* __restrict__ A,
                      const float* __restrict__ B,
                      const float* __restrict__ bias,
                      float* __restrict__ C,
                      int M, int N, int K) {
    constexpr int BK = 32;
    constexpr int THREADS = WARPS_M * WARPS_N * 32;
    constexpr int WM = BM / WARPS_M;       // 64
    constexpr int WN = BN / WARPS_N;       // 32
    constexpr int MT = WM / 16;            // 4
    constexpr int NT = WN / 8;             // 4
    constexpr int LDA = BM + 8;            // pad -> conflict-free frag loads
    constexpr int LDB = BN + 8;

    __shared__ unsigned As[BK * LDA];      // As[k][m], tf32
    __shared__ unsigned Bs[BK * LDB];      // Bs[k][n], tf32

    int tid = threadIdx.x;
    int lane = tid & 31;
    int warp = tid >> 5;
    int g  = lane >> 2;                    // group id 0..7
    int tg = lane & 3;                     // thread in group 0..3
    int wm = warp / WARPS_N;
    int wn = warp % WARPS_N;
    int rowBase = blockIdx.y * BM;
    int colBase = blockIdx.x * BN;
    int m_base = wm * WM;
    int n_base = wn * WN;

    float acc[MT][NT][4];
#pragma unroll
    for (int i = 0; i < MT; i++)
#pragma unroll
        for (int j = 0; j < NT; j++)
#pragma unroll
            for (int r = 0; r < 4; r++) acc[i][j][r] = 0.f;

    for (int k0 = 0; k0 < K; k0 += BK) {
        // Load A tile (BM x BK), transpose into As[k][m] as tf32
#pragma unroll
        for (int idx = tid * 4; idx < BM * BK; idx += THREADS * 4) {
            int r = idx / BK;          // m
            int c = idx % BK;          // k
            int grow = rowBase + r;
            float4 v = make_float4(0.f, 0.f, 0.f, 0.f);
            if (grow < M)
                v = *(const float4*)(A + (size_t)grow * K + k0 + c);
            As[(c + 0) * LDA + r] = f2tf32(v.x);
            As[(c + 1) * LDA + r] = f2tf32(v.y);
            As[(c + 2) * LDA + r] = f2tf32(v.z);
            As[(c + 3) * LDA + r] = f2tf32(v.w);
        }
        // Load B tile (BK x BN) as tf32
#pragma unroll
        for (int idx = tid * 4; idx < BK * BN; idx += THREADS * 4) {
            int r = idx / BN;          // k
            int c = idx % BN;          // n
            float4 v = *(const float4*)(B + (size_t)(k0 + r) * N + colBase + c);
            uint4 u;
            u.x = f2tf32(v.x); u.y = f2tf32(v.y);
            u.z = f2tf32(v.z); u.w = f2tf32(v.w);
            *(uint4*)&Bs[r * LDB + c] = u;
        }
        __syncthreads();

#pragma unroll
        for (int ks = 0; ks < BK / 8; ks++) {
            int k = ks * 8;
            unsigned a[MT][4];
#pragma unroll
            for (int mt = 0; mt < MT; mt++) {
                int m0 = m_base + mt * 16 + g;
                a[mt][0] = As[(k + tg) * LDA + m0];
                a[mt][1] = As[(k + tg) * LDA + m0 + 8];
                a[mt][2] = As[(k + tg + 4) * LDA + m0];
                a[mt][3] = As[(k + tg + 4) * LDA + m0 + 8];
            }
            unsigned b[NT][2];
#pragma unroll
            for (int nt = 0; nt < NT; nt++) {
                int n0 = n_base + nt * 8 + g;
                b[nt][0] = Bs[(k + tg) * LDB + n0];
                b[nt][1] = Bs[(k + tg + 4) * LDB + n0];
            }
#pragma unroll
            for (int mt = 0; mt < MT; mt++)
#pragma unroll
                for (int nt = 0; nt < NT; nt++) {
                    asm volatile(
                        "mma.sync.aligned.m16n8k8.row.col.f32.tf32.tf32.f32 "
                        "{%0,%1,%2,%3}, {%4,%5,%6,%7}, {%8,%9}, {%0,%1,%2,%3};"
                        : "+f"(acc[mt][nt][0]), "+f"(acc[mt][nt][1]),
                          "+f"(acc[mt][nt][2]), "+f"(acc[mt][nt][3])
                        : "r"(a[mt][0]), "r"(a[mt][1]), "r"(a[mt][2]), "r"(a[mt][3]),
                          "r"(b[nt][0]), "r"(b[nt][1]));
                }
        }
        __syncthreads();
    }

    // Epilogue
#pragma unroll
    for (int mt = 0; mt < MT; mt++) {
#pragma unroll
        for (int nt = 0; nt < NT; nt++) {
            int row0 = rowBase + m_base + mt * 16 + g;
            int col  = colBase + n_base + nt * 8 + 2 * tg;
            float2 v0 = make_float2(acc[mt][nt][0], acc[mt][nt][1]);
            float2 v1 = make_float2(acc[mt][nt][2], acc[mt][nt][3]);
            if constexpr (BIAS) {
                float2 bv = *(const float2*)(bias + col);
                v0.x += bv.x; v0.y += bv.y;
                v1.x += bv.x; v1.y += bv.y;
            }
            if (row0 < M)     *(float2*)(C + (size_t)row0 * N + col) = v0;
            if (row0 + 8 < M) *(float2*)(C + (size_t)(row0 + 8) * N + col) = v1;
        }
    }
}

// ---------------- Gather aggregation (warp per node), fused bias+self+ReLU ---
__global__ void aggregate_kernel(const float* __restrict__ xw,
                                 const float* __restrict__ bias,
                                 float* __restrict__ out) {
    int warp = (blockIdx.x * blockDim.x + threadIdx.x) >> 5;
    int lane = threadIdx.x & 31;
    if (warp >= NN) return;
    int i = warp;

    float di = g_dinv[i];
    float self = di * di;

    const float4* xrow = (const float4*)(xw + (size_t)i * HD);
    const float4* brow = (const float4*)bias;
    float4 acc[4];
#pragma unroll
    for (int c = 0; c < 4; c++) {
        float4 v = xrow[lane + 32 * c];
        float4 b = brow[lane + 32 * c];
        acc[c].x = fmaf(v.x, self, b.x);
        acc[c].y = fmaf(v.y, self, b.y);
        acc[c].z = fmaf(v.z, self, b.z);
        acc[c].w = fmaf(v.w, self, b.w);
    }

    int beg = g_off[i];
    int cnt = g_counts[i];
    for (int t = 0; t < cnt; t++) {
        int s = g_csr_src[beg + t];
        float w = g_dinv[s] * di;
        const float4* srow = (const float4*)(xw + (size_t)s * HD);
#pragma unroll
        for (int c = 0; c < 4; c++) {
            float4 v = srow[lane + 32 * c];
            acc[c].x = fmaf(v.x, w, acc[c].x);
            acc[c].y = fmaf(v.y, w, acc[c].y);
            acc[c].z = fmaf(v.z, w, acc[c].z);
            acc[c].w = fmaf(v.w, w, acc[c].w);
        }
    }

    float4* orow = (float4*)(out + (size_t)i * HD);
#pragma unroll
    for (int c = 0; c < 4; c++) {
        float4 v;
        v.x = fmaxf(acc[c].x, 0.f);
        v.y = fmaxf(acc[c].y, 0.f);
        v.z = fmaxf(acc[c].z, 0.f);
        v.w = fmaxf(acc[c].w, 0.f);
        orow[lane + 32 * c] = v;
    }
}

// ---------------- Launch -----------------------------------------------------
extern "C" void kernel_launch(void* const* d_in, const int* in_sizes, int n_in,
                              void* d_out, int out_size) {
    const float* x  = (const float*)d_in[0];
    const int*   ei = (const int*)d_in[1];   // int32 OR int64, detected on device
    const float* W1 = (const float*)d_in[2];
    const float* b1 = (const float*)d_in[3];
    const float* W2 = (const float*)d_in[4];
    const float* b2 = (const float*)d_in[5];
    const float* Wl = (const float*)d_in[6];
    const float* bl = (const float*)d_in[7];
    float* out = (float*)d_out;

    float* xw;  cudaGetSymbolAddress((void**)&xw, g_xw);
    float* h;   cudaGetSymbolAddress((void**)&h,  g_h);

    // Graph prep
    detect_kernel<<<1, 256>>>(ei);
    zero_counts_kernel<<<(NN + 255) / 256, 256>>>();
    convert_edges_kernel<<<(EE + 255) / 256, 256>>>(ei);
    dinv_kernel<<<(NN + 255) / 256, 256>>>();
    scan1_kernel<<<SCAN_NBLK, SCAN_BLK>>>();
    scan2_kernel<<<1, 32>>>();
    scan3_kernel<<<SCAN_NBLK, SCAN_BLK>>>();
    scatter_kernel<<<(EE + 255) / 256, 256>>>();

    // Layer 1: xw = x @ W1 ; h = relu(aggregate(xw) + b1)
    {
        dim3 grid(HD / 128, (NN + 127) / 128);
        tf32_gemm_kernel<128, 128, 2, 4, false><<<grid, 256>>>(x, W1, nullptr, xw, NN, HD, IND);
        aggregate_kernel<<<(NN * 32 + 255) / 256, 256>>>(xw, b1, h);
    }
    // Layer 2: xw = h @ W2 ; h = relu(aggregate(xw) + b2)
    {
        dim3 grid(HD / 128, (NN + 127) / 128);
        tf32_gemm_kernel<128, 128, 2, 4, false><<<grid, 256>>>(h, W2, nullptr, xw, NN, HD, HD);
        aggregate_kernel<<<(NN * 32 + 255) / 256, 256>>>(xw, b2, h);
    }
    // Output: out = h @ Wl + bl
    {
        dim3 grid(OUTD / 64, (NN + 127) / 128);
        tf32_gemm_kernel<128, 64, 2, 2, true><<<grid, 128>>>(h, Wl, bl, out, NN, OUTD, HD);
    }
}

// round 4
// speedup vs baseline: 1.9510x; 1.1875x over previous
#include <cuda_runtime.h>
#include <cuda_fp16.h>
#include <cstdint>

// Problem constants
#define NN 50000
#define EE 800000
#define HD 512
#define IND 256
#define OUTD 64

// ---------------- Scratch (static device globals; no allocation APIs) -------
__device__ __align__(16) int    g_src[EE];
__device__ __align__(16) int    g_dst[EE];
__device__ __align__(16) int    g_counts[NN];
__device__ __align__(16) int    g_off[NN + 1];
__device__ __align__(16) int    g_cursor[NN];
__device__ __align__(16) float  g_dinv[NN];
__device__ __align__(16) int    g_csr_src[EE];
__device__ __align__(16) __half g_xw[(size_t)NN * HD];  // 51.2 MB (L2-resident)
__device__ __align__(16) float  g_h[(size_t)NN * HD];   // 102.4 MB
__device__ int g_flag;            // 1 = edge_index stored as int64, 0 = int32
__device__ int g_blocksums[64];

// ---------------- Edge dtype detection --------------------------------------
__global__ void detect_kernel(const int* __restrict__ raw) {
    __shared__ int any;
    if (threadIdx.x == 0) any = 0;
    __syncthreads();
    int v = raw[2 * threadIdx.x + 1];
    if (v != 0) atomicOr(&any, 1);
    __syncthreads();
    if (threadIdx.x == 0) g_flag = any ? 0 : 1;
}

__global__ void zero_counts_kernel() {
    int i = blockIdx.x * blockDim.x + threadIdx.x;
    if (i < NN) { g_counts[i] = 0; g_cursor[i] = 0; }
}

__global__ void convert_edges_kernel(const int* __restrict__ raw) {
    int e = blockIdx.x * blockDim.x + threadIdx.x;
    if (e >= EE) return;
    int s, d;
    if (g_flag) { s = raw[2 * e]; d = raw[2 * (EE + e)]; }
    else        { s = raw[e];     d = raw[EE + e]; }
    g_src[e] = s;
    g_dst[e] = d;
    atomicAdd(&g_counts[d], 1);
}

__global__ void dinv_kernel() {
    int i = blockIdx.x * blockDim.x + threadIdx.x;
    if (i < NN) g_dinv[i] = rsqrtf((float)(g_counts[i] + 1));  // +1 self-loop
}

// ---------------- Exclusive scan of counts -> offsets ------------------------
#define SCAN_BLK 1024
#define SCAN_NBLK ((NN + SCAN_BLK - 1) / SCAN_BLK)   // 49

__global__ void scan1_kernel() {
    __shared__ int s[SCAN_BLK];
    int i = blockIdx.x * SCAN_BLK + threadIdx.x;
    int v = (i < NN) ? g_counts[i] : 0;
    s[threadIdx.x] = v;
    __syncthreads();
    for (int d = 1; d < SCAN_BLK; d <<= 1) {
        int t = (threadIdx.x >= d) ? s[threadIdx.x - d] : 0;
        __syncthreads();
        s[threadIdx.x] += t;
        __syncthreads();
    }
    if (i < NN) g_off[i] = s[threadIdx.x] - v;   // exclusive within block
    if (threadIdx.x == SCAN_BLK - 1) g_blocksums[blockIdx.x] = s[SCAN_BLK - 1];
}

__global__ void scan2_kernel() {
    if (threadIdx.x == 0) {
        int acc = 0;
        for (int b = 0; b < SCAN_NBLK; b++) {
            int t = g_blocksums[b];
            g_blocksums[b] = acc;
            acc += t;
        }
    }
}

__global__ void scan3_kernel() {
    int i = blockIdx.x * SCAN_BLK + threadIdx.x;
    if (i < NN) g_off[i] += g_blocksums[blockIdx.x];
    if (i == 0) g_off[NN] = EE;
}

__global__ void scatter_kernel() {
    int e = blockIdx.x * blockDim.x + threadIdx.x;
    if (e >= EE) return;
    int d = g_dst[e];
    int pos = g_off[d] + atomicAdd(&g_cursor[d], 1);
    g_csr_src[pos] = g_src[e];
}

// ---------------- TF32 tensor-core GEMM --------------------------------------
// C[M,N] = A[M,K] @ B[K,N] (+ bias). A,B row-major fp32. K % 32 == 0, N % BN == 0.
// OUT_HALF: write C as fp16. Register-staged 2-stage pipeline.
__device__ __forceinline__ unsigned f2tf32(float x) {
    unsigned r;
    asm("cvt.rna.tf32.f32 %0, %1;" : "=r"(r) : "f"(x));
    return r;
}

template <int BM, int BN, int WARPS_M, int WARPS_N, bool OUT_HALF, bool BIAS>
__global__ __launch_bounds__(WARPS_M * WARPS_N * 32)
void tf32_gemm_kernel(const float* __restrict__ A,
                      const float* __restrict__ B,
                      const float* __restrict__ bias,
                      void* __restrict__ Cv,
                      int M, int N, int K) {
    constexpr int BK = 32;
    constexpr int THREADS = WARPS_M * WARPS_N * 32;
    constexpr int WM = BM / WARPS_M;       // 64
    constexpr int WN = BN / WARPS_N;       // 32
    constexpr int MT = WM / 16;            // 4
    constexpr int NT = WN / 8;             // 4
    constexpr int LDA = BM + 4;            // frag loads conflict-free: 4*tg+g distinct
    constexpr int LDB = BN + 4;
    constexpr int A_F4 = BM * BK / (THREADS * 4);  // float4 per thread (A tile)
    constexpr int B_F4 = BK * BN / (THREADS * 4);

    __shared__ unsigned As[BK * LDA];      // As[k][m], tf32
    __shared__ unsigned Bs[BK * LDB];      // Bs[k][n], tf32

    int tid = threadIdx.x;
    int lane = tid & 31;
    int warp = tid >> 5;
    int g  = lane >> 2;                    // group id 0..7
    int tg = lane & 3;                     // thread in group 0..3
    int wm = warp / WARPS_N;
    int wn = warp % WARPS_N;
    int rowBase = blockIdx.y * BM;
    int colBase = blockIdx.x * BN;
    int m_base = wm * WM;
    int n_base = wn * WN;

    float acc[MT][NT][4];
#pragma unroll
    for (int i = 0; i < MT; i++)
#pragma unroll
        for (int j = 0; j < NT; j++)
#pragma unroll
            for (int r = 0; r < 4; r++) acc[i][j][r] = 0.f;

    float4 ra[A_F4], rb[B_F4];

    auto load_tile = [&](int k0) {
#pragma unroll
        for (int u = 0; u < A_F4; u++) {
            int idx = (tid + u * THREADS) * 4;
            int r = idx / BK, c = idx % BK;
            int grow = rowBase + r;
            ra[u] = (grow < M) ? *(const float4*)(A + (size_t)grow * K + k0 + c)
                               : make_float4(0.f, 0.f, 0.f, 0.f);
        }
#pragma unroll
        for (int u = 0; u < B_F4; u++) {
            int idx = (tid + u * THREADS) * 4;
            int r = idx / BN, c = idx % BN;
            rb[u] = *(const float4*)(B + (size_t)(k0 + r) * N + colBase + c);
        }
    };
    auto store_tile = [&]() {
#pragma unroll
        for (int u = 0; u < A_F4; u++) {
            int idx = (tid + u * THREADS) * 4;
            int r = idx / BK, c = idx % BK;
            As[(c + 0) * LDA + r] = f2tf32(ra[u].x);
            As[(c + 1) * LDA + r] = f2tf32(ra[u].y);
            As[(c + 2) * LDA + r] = f2tf32(ra[u].z);
            As[(c + 3) * LDA + r] = f2tf32(ra[u].w);
        }
#pragma unroll
        for (int u = 0; u < B_F4; u++) {
            int idx = (tid + u * THREADS) * 4;
            int r = idx / BN, c = idx % BN;
            uint4 q;
            q.x = f2tf32(rb[u].x); q.y = f2tf32(rb[u].y);
            q.z = f2tf32(rb[u].z); q.w = f2tf32(rb[u].w);
            *(uint4*)&Bs[r * LDB + c] = q;
        }
    };

    load_tile(0);
    store_tile();
    __syncthreads();

    int nIter = K / BK;
    for (int it = 0; it < nIter; it++) {
        if (it + 1 < nIter) load_tile((it + 1) * BK);   // prefetch (global)

#pragma unroll
        for (int ks = 0; ks < BK / 8; ks++) {
            int k = ks * 8;
            unsigned a[MT][4];
#pragma unroll
            for (int mt = 0; mt < MT; mt++) {
                int m0 = m_base + mt * 16 + g;
                a[mt][0] = As[(k + tg) * LDA + m0];
                a[mt][1] = As[(k + tg) * LDA + m0 + 8];
                a[mt][2] = As[(k + tg + 4) * LDA + m0];
                a[mt][3] = As[(k + tg + 4) * LDA + m0 + 8];
            }
            unsigned b[NT][2];
#pragma unroll
            for (int nt = 0; nt < NT; nt++) {
                int n0 = n_base + nt * 8 + g;
                b[nt][0] = Bs[(k + tg) * LDB + n0];
                b[nt][1] = Bs[(k + tg + 4) * LDB + n0];
            }
#pragma unroll
            for (int mt = 0; mt < MT; mt++)
#pragma unroll
                for (int nt = 0; nt < NT; nt++) {
                    asm volatile(
                        "mma.sync.aligned.m16n8k8.row.col.f32.tf32.tf32.f32 "
                        "{%0,%1,%2,%3}, {%4,%5,%6,%7}, {%8,%9}, {%0,%1,%2,%3};"
                        : "+f"(acc[mt][nt][0]), "+f"(acc[mt][nt][1]),
                          "+f"(acc[mt][nt][2]), "+f"(acc[mt][nt][3])
                        : "r"(a[mt][0]), "r"(a[mt][1]), "r"(a[mt][2]), "r"(a[mt][3]),
                          "r"(b[nt][0]), "r"(b[nt][1]));
                }
        }
        __syncthreads();
        if (it + 1 < nIter) {
            store_tile();
            __syncthreads();
        }
    }

    // Epilogue
#pragma unroll
    for (int mt = 0; mt < MT; mt++) {
#pragma unroll
        for (int nt = 0; nt < NT; nt++) {
            int row0 = rowBase + m_base + mt * 16 + g;
            int col  = colBase + n_base + nt * 8 + 2 * tg;
            float2 v0 = make_float2(acc[mt][nt][0], acc[mt][nt][1]);
            float2 v1 = make_float2(acc[mt][nt][2], acc[mt][nt][3]);
            if constexpr (BIAS) {
                float2 bv = *(const float2*)(bias + col);
                v0.x += bv.x; v0.y += bv.y;
                v1.x += bv.x; v1.y += bv.y;
            }
            if constexpr (OUT_HALF) {
                __half* C = (__half*)Cv;
                if (row0 < M)
                    *(__half2*)(C + (size_t)row0 * N + col) = __floats2half2_rn(v0.x, v0.y);
                if (row0 + 8 < M)
                    *(__half2*)(C + (size_t)(row0 + 8) * N + col) = __floats2half2_rn(v1.x, v1.y);
            } else {
                float* C = (float*)Cv;
                if (row0 < M)     *(float2*)(C + (size_t)row0 * N + col) = v0;
                if (row0 + 8 < M) *(float2*)(C + (size_t)(row0 + 8) * N + col) = v1;
            }
        }
    }
}

// ---------------- Gather aggregation (warp per node), fp16 table -------------
// out = relu(sum_{s in N(i)} w_si * xw[s] + dii*xw[i] + bias), fp32 accum/out.
__global__ void aggregate_kernel(const __half* __restrict__ xw,
                                 const float* __restrict__ bias,
                                 float* __restrict__ out) {
    int warp = (blockIdx.x * blockDim.x + threadIdx.x) >> 5;
    int lane = threadIdx.x & 31;
    if (warp >= NN) return;
    int i = warp;

    float di = g_dinv[i];
    float self = di * di;

    // Row = 512 halves = 64 uint4; lane owns uint4 indices {lane, lane+32}.
    float acc[2][8];
    {
        const uint4* xrow = (const uint4*)(xw + (size_t)i * HD);
#pragma unroll
        for (int c = 0; c < 2; c++) {
            uint4 v = xrow[lane + 32 * c];
            const __half2* h2 = (const __half2*)&v;
            const float4* b4 = (const float4*)(bias + 8 * (lane + 32 * c));
            float4 b0 = b4[0], b1 = b4[1];
            float2 f0 = __half22float2(h2[0]);
            float2 f1 = __half22float2(h2[1]);
            float2 f2 = __half22float2(h2[2]);
            float2 f3 = __half22float2(h2[3]);
            acc[c][0] = fmaf(f0.x, self, b0.x);
            acc[c][1] = fmaf(f0.y, self, b0.y);
            acc[c][2] = fmaf(f1.x, self, b0.z);
            acc[c][3] = fmaf(f1.y, self, b0.w);
            acc[c][4] = fmaf(f2.x, self, b1.x);
            acc[c][5] = fmaf(f2.y, self, b1.y);
            acc[c][6] = fmaf(f3.x, self, b1.z);
            acc[c][7] = fmaf(f3.y, self, b1.w);
        }
    }

    int beg = g_off[i];
    int cnt = g_counts[i];
    for (int t = 0; t < cnt; t++) {
        int s = g_csr_src[beg + t];
        float w = g_dinv[s] * di;
        const uint4* srow = (const uint4*)(xw + (size_t)s * HD);
        uint4 v0 = srow[lane];
        uint4 v1 = srow[lane + 32];
#pragma unroll
        for (int c = 0; c < 2; c++) {
            uint4 v = c ? v1 : v0;
            const __half2* h2 = (const __half2*)&v;
#pragma unroll
            for (int q = 0; q < 4; q++) {
                float2 f = __half22float2(h2[q]);
                acc[c][2 * q + 0] = fmaf(f.x, w, acc[c][2 * q + 0]);
                acc[c][2 * q + 1] = fmaf(f.y, w, acc[c][2 * q + 1]);
            }
        }
    }

#pragma unroll
    for (int c = 0; c < 2; c++) {
        float4* orow = (float4*)(out + (size_t)i * HD + 8 * (lane + 32 * c));
        float4 o0, o1;
        o0.x = fmaxf(acc[c][0], 0.f); o0.y = fmaxf(acc[c][1], 0.f);
        o0.z = fmaxf(acc[c][2], 0.f); o0.w = fmaxf(acc[c][3], 0.f);
        o1.x = fmaxf(acc[c][4], 0.f); o1.y = fmaxf(acc[c][5], 0.f);
        o1.z = fmaxf(acc[c][6], 0.f); o1.w = fmaxf(acc[c][7], 0.f);
        orow[0] = o0;
        orow[1] = o1;
    }
}

// ---------------- Launch -----------------------------------------------------
extern "C" void kernel_launch(void* const* d_in, const int* in_sizes, int n_in,
                              void* d_out, int out_size) {
    const float* x  = (const float*)d_in[0];
    const int*   ei = (const int*)d_in[1];   // int32 OR int64, detected on device
    const float* W1 = (const float*)d_in[2];
    const float* b1 = (const float*)d_in[3];
    const float* W2 = (const float*)d_in[4];
    const float* b2 = (const float*)d_in[5];
    const float* Wl = (const float*)d_in[6];
    const float* bl = (const float*)d_in[7];
    float* out = (float*)d_out;

    __half* xw; cudaGetSymbolAddress((void**)&xw, g_xw);
    float*  h;  cudaGetSymbolAddress((void**)&h,  g_h);

    // Graph prep
    detect_kernel<<<1, 256>>>(ei);
    zero_counts_kernel<<<(NN + 255) / 256, 256>>>();
    convert_edges_kernel<<<(EE + 255) / 256, 256>>>(ei);
    dinv_kernel<<<(NN + 255) / 256, 256>>>();
    scan1_kernel<<<SCAN_NBLK, SCAN_BLK>>>();
    scan2_kernel<<<1, 32>>>();
    scan3_kernel<<<SCAN_NBLK, SCAN_BLK>>>();
    scatter_kernel<<<(EE + 255) / 256, 256>>>();

    // Layer 1: xw = fp16(x @ W1) ; h = relu(aggregate(xw) + b1)
    {
        dim3 grid(HD / 128, (NN + 127) / 128);
        tf32_gemm_kernel<128, 128, 2, 4, true, false><<<grid, 256>>>(x, W1, nullptr, xw, NN, HD, IND);
        aggregate_kernel<<<(NN * 32 + 255) / 256, 256>>>(xw, b1, h);
    }
    // Layer 2: xw = fp16(h @ W2) ; h = relu(aggregate(xw) + b2)
    {
        dim3 grid(HD / 128, (NN + 127) / 128);
        tf32_gemm_kernel<128, 128, 2, 4, true, false><<<grid, 256>>>(h, W2, nullptr, xw, NN, HD, HD);
        aggregate_kernel<<<(NN * 32 + 255) / 256, 256>>>(xw, b2, h);
    }
    // Output: out = h @ Wl + bl (fp32)
    {
        dim3 grid(OUTD / 64, (NN + 127) / 128);
        tf32_gemm_kernel<128, 64, 2, 2, false, true><<<grid, 128>>>(h, Wl, bl, out, NN, OUTD, HD);
    }
}